// round 7
// baseline (speedup 1.0000x reference)
#include <cuda_runtime.h>

#define IMG      512
#define TW       64
#define TH       32
#define HROWS    42
#define HSTRIDE  66          // 528B row stride, 16B-aligned float4 stores
#define NT       256
#define NPLANES  192
#define NBLOCKS  (8 * 16 * 192)
#define NPIX     (64.0 * 3.0 * 512.0 * 512.0)

typedef unsigned long long u64;

__device__ constexpr float GW[6] = {
    1.0283886e-3f, 7.5988485e-3f, 3.6000773e-2f, 1.0936073e-1f, 2.1300553e-1f,
    2.6601180e-1f
};

#define C1F 4.0e-4f
#define C2F 3.6e-3f

__device__ double g_acc[2];
__device__ unsigned int g_count;

// ---------- packed f32x2 helpers ----------
__device__ __forceinline__ u64 pk2(float lo, float hi) {
    u64 r; asm("mov.b64 %0,{%1,%2};" : "=l"(r) : "f"(lo), "f"(hi)); return r;
}
__device__ __forceinline__ void upk(u64 a, float& lo, float& hi) {
    asm("mov.b64 {%0,%1},%2;" : "=f"(lo), "=f"(hi) : "l"(a));
}
__device__ __forceinline__ u64 f2fma(u64 a, u64 b, u64 c) {
    u64 d; asm("fma.rn.f32x2 %0,%1,%2,%3;" : "=l"(d) : "l"(a), "l"(b), "l"(c)); return d;
}
__device__ __forceinline__ u64 f2add(u64 a, u64 b) {
    u64 d; asm("add.rn.f32x2 %0,%1,%2;" : "=l"(d) : "l"(a), "l"(b)); return d;
}
__device__ __forceinline__ u64 f2mul(u64 a, u64 b) {
    u64 d; asm("mul.rn.f32x2 %0,%1,%2;" : "=l"(d) : "l"(a), "l"(b)); return d;
}

// 11-tap symmetric conv on packed pairs
__device__ __forceinline__ u64 conv11(const u64* w, const u64* G2) {
    u64 acc = f2mul(G2[5], w[5]);
#pragma unroll
    for (int k = 0; k < 5; k++)
        acc = f2fma(G2[k], f2add(w[k], w[10 - k]), acc);
    return acc;
}

// conv + store two streams of N outputs, pairwise (keeps live regs low)
template <int N>
__device__ __forceinline__ void convStoreRow(
    u64* w, u64* Hrow_sd, u64* Hrow_uv, const u64* G2, int nwin)
{
    // SD stream
#pragma unroll
    for (int j = 0; j < N; j += 2) {
        u64 o0 = conv11(w + j, G2), o1 = conv11(w + j + 1, G2);
        float a0, b0, a1, b1;
        upk(o0, a0, b0); upk(o1, a1, b1);
        *reinterpret_cast<float4*>(Hrow_sd + j) = make_float4(a0, b0, a1, b1);
    }
    // square in place, then UV stream
#pragma unroll
    for (int m = 0; m < 18; m++) { if (m < nwin) w[m] = f2mul(w[m], w[m]); }
#pragma unroll
    for (int j = 0; j < N; j += 2) {
        u64 o0 = conv11(w + j, G2), o1 = conv11(w + j + 1, G2);
        float a0, b0, a1, b1;
        upk(o0, a0, b0); upk(o1, a1, b1);
        *reinterpret_cast<float4*>(Hrow_uv + j) = make_float4(a0, b0, a1, b1);
    }
}

// ---------------- Phase A full slot: rows 0..31, 8 outputs ----------------
// MODE 0: interior. MODE 1: row-guard only. MODE 2: row+col guards.
template <int MODE>
__device__ __forceinline__ u64 fullSlot(
    const float* __restrict__ xp, const float* __restrict__ yp,
    int row0, int col0, int tid,
    u64 (*Hsd)[HSTRIDE], u64 (*Huv)[HSTRIDE], const u64* G2)
{
    const int r = tid >> 3;            // 0..31
    const int g = tid & 7;
    const int rimg = row0 - 5 + r;
    const int cb   = col0 + g * 8 - 8; // 32B-aligned; window cols cb+3..cb+20

    u64 w[18];
    bool vec;
    if (MODE == 0) vec = true;
    else {
        const bool rok = ((unsigned)rimg < IMG);
        if (MODE == 1) vec = rok;
        else vec = rok && (cb >= 0) && (cb + 24 <= IMG);
        if (!vec) {
            if ((MODE == 2) && rok) {
#pragma unroll
                for (int m = 0; m < 18; m++) {
                    const int c = cb + 3 + m;
                    float xv = 0.f, yv = 0.f;
                    if ((unsigned)c < IMG) {
                        xv = __ldg(xp + (size_t)rimg * IMG + c);
                        yv = __ldg(yp + (size_t)rimg * IMG + c);
                    }
                    w[m] = pk2(xv + yv, xv - yv);
                }
            } else {
#pragma unroll
                for (int m = 0; m < 18; m++) w[m] = 0;
            }
            goto havewin;
        }
    }
    {
        const float4* xr = reinterpret_cast<const float4*>(xp + (size_t)rimg * IMG + cb);
        const float4* yr = reinterpret_cast<const float4*>(yp + (size_t)rimg * IMG + cb);
#pragma unroll
        for (int v = 0; v < 6; v++) {
            const float4 fx = __ldg(xr + v);
            const float4 fy = __ldg(yr + v);
            const float xe[4] = { fx.x, fx.y, fx.z, fx.w };
            const float ye[4] = { fy.x, fy.y, fy.z, fy.w };
#pragma unroll
            for (int e = 0; e < 4; e++) {
                const int i = 4 * v + e;           // col cb+i; window i in [3,21)
                if (i >= 3 && i < 21)
                    w[i - 3] = pk2(xe[e] + ye[e], xe[e] - ye[e]);
            }
        }
    }
havewin:
    u64 msep = 0;
    if (r >= 5) {                       // owned rows; owned cols -> w[5..12]
#pragma unroll
        for (int m = 5; m < 13; m++) msep = f2fma(w[m], w[m], msep);
    }
    convStoreRow<8>(w, &Hsd[r][g * 8], &Huv[r][g * 8], G2, 18);
    return msep;
}

// ---------------- Phase A quarter slot: rows 32..41, 4 outputs ----------------
template <int MODE>
__device__ __forceinline__ u64 quarterSlot(
    const float* __restrict__ xp, const float* __restrict__ yp,
    int row0, int col0, int tid,
    u64 (*Hsd)[HSTRIDE], u64 (*Huv)[HSTRIDE], const u64* G2)
{
    const int r = 32 + (tid >> 4);     // 32..41
    const int q = tid & 15;
    const int rimg = row0 - 5 + r;
    const int cb   = col0 + q * 4 - 8; // 16B-aligned; window cols cb+3..cb+16

    u64 w[18];                          // only 14 used
    bool vec;
    if (MODE == 0) vec = true;
    else {
        const bool rok = ((unsigned)rimg < IMG);
        if (MODE == 1) vec = rok;
        else vec = rok && (cb >= 0) && (cb + 20 <= IMG);
        if (!vec) {
            if ((MODE == 2) && rok) {
#pragma unroll
                for (int m = 0; m < 14; m++) {
                    const int c = cb + 3 + m;
                    float xv = 0.f, yv = 0.f;
                    if ((unsigned)c < IMG) {
                        xv = __ldg(xp + (size_t)rimg * IMG + c);
                        yv = __ldg(yp + (size_t)rimg * IMG + c);
                    }
                    w[m] = pk2(xv + yv, xv - yv);
                }
            } else {
#pragma unroll
                for (int m = 0; m < 14; m++) w[m] = 0;
            }
            goto havewin;
        }
    }
    {
        const float4* xr = reinterpret_cast<const float4*>(xp + (size_t)rimg * IMG + cb);
        const float4* yr = reinterpret_cast<const float4*>(yp + (size_t)rimg * IMG + cb);
#pragma unroll
        for (int v = 0; v < 5; v++) {
            const float4 fx = __ldg(xr + v);
            const float4 fy = __ldg(yr + v);
            const float xe[4] = { fx.x, fx.y, fx.z, fx.w };
            const float ye[4] = { fy.x, fy.y, fy.z, fy.w };
#pragma unroll
            for (int e = 0; e < 4; e++) {
                const int i = 4 * v + e;           // window i in [3,17)
                if (i >= 3 && i < 17)
                    w[i - 3] = pk2(xe[e] + ye[e], xe[e] - ye[e]);
            }
        }
    }
havewin:
    u64 msep = 0;
    if (r < 37) {                       // owned rows 32..36
#pragma unroll
        for (int m = 5; m < 9; m++) msep = f2fma(w[m], w[m], msep);
    }
    convStoreRow<4>(w, &Hsd[r][q * 4], &Huv[r][q * 4], G2, 14);
    return msep;
}

__global__ void __launch_bounds__(NT, 4) ssim_mse_kernel(
    const float* __restrict__ x, const float* __restrict__ y,
    float* __restrict__ out)
{
    __shared__ alignas(16) u64 Hsd[HROWS][HSTRIDE];
    __shared__ alignas(16) u64 Huv[HROWS][HSTRIDE];
    __shared__ float red_m[8], red_s[8];

    const int plane = blockIdx.z;
    const int row0  = blockIdx.y * TH;
    const int col0  = blockIdx.x * TW;
    const float* xp = x + (size_t)plane * (IMG * IMG);
    const float* yp = y + (size_t)plane * (IMG * IMG);
    const int tid = threadIdx.x;

    const u64 G2[6] = { pk2(GW[0], GW[0]), pk2(GW[1], GW[1]), pk2(GW[2], GW[2]),
                        pk2(GW[3], GW[3]), pk2(GW[4], GW[4]), pk2(GW[5], GW[5]) };

    const bool xin = (blockIdx.x >= 1) && (blockIdx.x <= 6);
    const bool yin = (blockIdx.y >= 1) && (blockIdx.y <= 14);

    u64 msep;
    if (xin && yin) {
        msep = fullSlot<0>(xp, yp, row0, col0, tid, Hsd, Huv, G2);
        if (tid < 160)
            msep = f2add(msep, quarterSlot<0>(xp, yp, row0, col0, tid, Hsd, Huv, G2));
    } else if (xin) {
        msep = fullSlot<1>(xp, yp, row0, col0, tid, Hsd, Huv, G2);
        if (tid < 160)
            msep = f2add(msep, quarterSlot<1>(xp, yp, row0, col0, tid, Hsd, Huv, G2));
    } else {
        msep = fullSlot<2>(xp, yp, row0, col0, tid, Hsd, Huv, G2);
        if (tid < 160)
            msep = f2add(msep, quarterSlot<2>(xp, yp, row0, col0, tid, Hsd, Huv, G2));
    }

    float mse_lo, mse_acc;
    upk(msep, mse_lo, mse_acc);        // hi lane = sum D^2

    __syncthreads();

    // ---------------- Phase B: two-pass vertical conv ----------------
    const int col   = tid & 63;
    const int strip = tid >> 6;
    const int rb    = strip * 8;

    u64 ring[11];
    u64 vsd[8];

    // pass 1: SD stream
#pragma unroll
    for (int k = 0; k < 10; k++) ring[k] = Hsd[rb + k][col];
#pragma unroll
    for (int r = 0; r < 8; r++) {
        ring[(r + 10) % 11] = Hsd[rb + r + 10][col];
        u64 acc = f2mul(G2[5], ring[(r + 5) % 11]);
#pragma unroll
        for (int k = 0; k < 5; k++)
            acc = f2fma(G2[k], f2add(ring[(r + k) % 11], ring[(r + 10 - k) % 11]), acc);
        vsd[r] = acc;
    }

    // pass 2: UV stream + epilogue
    float ssim_acc = 0.f;
#pragma unroll
    for (int k = 0; k < 10; k++) ring[k] = Huv[rb + k][col];
#pragma unroll
    for (int r = 0; r < 8; r++) {
        ring[(r + 10) % 11] = Huv[rb + r + 10][col];
        u64 acc = f2mul(G2[5], ring[(r + 5) % 11]);
#pragma unroll
        for (int k = 0; k < 5; k++)
            acc = f2fma(G2[k], f2add(ring[(r + k) % 11], ring[(r + 10 - k) % 11]), acc);

        float U, V, S2, D2;
        upk(acc, U, V);
        upk(f2mul(vsd[r], vsd[r]), S2, D2);
        const float varS = U - S2;
        const float varD = V - D2;
        const float A   = 0.5f * (S2 - D2);  // 2*mu1*mu2
        const float Msq = 0.5f * (S2 + D2);  // mu1^2 + mu2^2
        const float num = (A + C1F) * (0.5f * (varS - varD) + C2F);
        const float den = (Msq + C1F) * (0.5f * (varS + varD) + C2F);
        ssim_acc += __fdividef(num, den);
    }

    // ---------------- Reduction + fused finalize ----------------
#pragma unroll
    for (int o = 16; o > 0; o >>= 1) {
        mse_acc  += __shfl_down_sync(0xffffffffu, mse_acc,  o);
        ssim_acc += __shfl_down_sync(0xffffffffu, ssim_acc, o);
    }
    const int wid = tid >> 5;
    if ((tid & 31) == 0) { red_m[wid] = mse_acc; red_s[wid] = ssim_acc; }
    __syncthreads();
    if (tid < 32) {
        float m  = (tid < 8) ? red_m[tid] : 0.f;
        float ss = (tid < 8) ? red_s[tid] : 0.f;
#pragma unroll
        for (int o = 4; o > 0; o >>= 1) {
            m  += __shfl_down_sync(0xffffffffu, m,  o);
            ss += __shfl_down_sync(0xffffffffu, ss, o);
        }
        if (tid == 0) {
            atomicAdd(&g_acc[0], (double)m);
            atomicAdd(&g_acc[1], (double)ss);
            __threadfence();
            const unsigned c = atomicAdd(&g_count, 1u);
            if (c == NBLOCKS - 1) {
                __threadfence();
                const double mse  = g_acc[0] / NPIX;
                const double ssim = g_acc[1] / NPIX;
                out[0] = (float)(0.7 * mse + 0.3 * (1.0 - ssim));
                g_acc[0] = 0.0;
                g_acc[1] = 0.0;
                __threadfence();
                g_count = 0u;
            }
        }
    }
}

extern "C" void kernel_launch(void* const* d_in, const int* in_sizes, int n_in,
                              void* d_out, int out_size)
{
    const float* recon = (const float*)d_in[0];
    const float* orig  = (const float*)d_in[1];
    float* out = (float*)d_out;

    dim3 grid(IMG / TW, IMG / TH, NPLANES);   // 24576 blocks
    ssim_mse_kernel<<<grid, NT>>>(recon, orig, out);
}

// round 8
// speedup vs baseline: 1.7398x; 1.7398x over previous
#include <cuda_runtime.h>

#define IMG      512
#define TW       64
#define TH       32
#define HROWS    42
#define HSTRIDE  66          // 528B row stride, 16B-aligned float4 stores
#define NT       256
#define NPLANES  192
#define NBLOCKS  (8 * 16 * 192)
#define NPIX     (64.0 * 3.0 * 512.0 * 512.0)

typedef unsigned long long u64;

__device__ constexpr float GW[6] = {
    1.0283886e-3f, 7.5988485e-3f, 3.6000773e-2f, 1.0936073e-1f, 2.1300553e-1f,
    2.6601180e-1f
};

#define C1F 4.0e-4f
#define C2F 3.6e-3f

__device__ double g_acc[2];
__device__ unsigned int g_count;

// ---------- packed f32x2 helpers ----------
__device__ __forceinline__ u64 pk2(float lo, float hi) {
    u64 r; asm("mov.b64 %0,{%1,%2};" : "=l"(r) : "f"(lo), "f"(hi)); return r;
}
__device__ __forceinline__ void upk(u64 a, float& lo, float& hi) {
    asm("mov.b64 {%0,%1},%2;" : "=f"(lo), "=f"(hi) : "l"(a));
}
__device__ __forceinline__ u64 f2fma(u64 a, u64 b, u64 c) {
    u64 d; asm("fma.rn.f32x2 %0,%1,%2,%3;" : "=l"(d) : "l"(a), "l"(b), "l"(c)); return d;
}
__device__ __forceinline__ u64 f2add(u64 a, u64 b) {
    u64 d; asm("add.rn.f32x2 %0,%1,%2;" : "=l"(d) : "l"(a), "l"(b)); return d;
}
__device__ __forceinline__ u64 f2mul(u64 a, u64 b) {
    u64 d; asm("mul.rn.f32x2 %0,%1,%2;" : "=l"(d) : "l"(a), "l"(b)); return d;
}

// 11-tap symmetric conv on packed pairs
__device__ __forceinline__ u64 conv11(const u64* w, const u64* G2) {
    u64 acc = f2mul(G2[5], w[5]);
#pragma unroll
    for (int k = 0; k < 5; k++)
        acc = f2fma(G2[k], f2add(w[k], w[10 - k]), acc);
    return acc;
}

// ---------------- Phase A: uniform 4-output slots ----------------
// Streams: SD = (x+y, x-y); UV = ((x+y)^2, (x-y)^2) derived in place.
// MODE 0: interior. MODE 1: row-guard only. MODE 2: row+col guards.
template <int MODE>
__device__ __forceinline__ u64 phaseA(
    const float* __restrict__ xp, const float* __restrict__ yp,
    int row0, int col0, int tid,
    u64 (*Hsd)[HSTRIDE], u64 (*Huv)[HSTRIDE], const u64* G2, u64 PM1)
{
    u64 msep = 0;
#pragma unroll
    for (int kk = 0; kk < 3; kk++) {
        const int s = tid + kk * NT;
        if (kk == 2 && s >= 672) break;
        const int r = s >> 4;          // 0..41
        const int q = s & 15;          // 0..15
        const int rimg = row0 - 5 + r;
        const int cb   = col0 + q * 4 - 8;   // 16B aligned

        u64 wsd[14];
        bool vec;
        if (MODE == 0) vec = true;
        else {
            const bool rok = ((unsigned)rimg < IMG);
            if (MODE == 1) vec = rok;
            else vec = rok && (cb >= 0) && (cb + 20 <= IMG);
            if (!vec && (MODE == 2) && rok) {
#pragma unroll
                for (int m = 0; m < 14; m++) {
                    const int c = cb + 3 + m;
                    float xv = 0.f, yv = 0.f;
                    if ((unsigned)c < IMG) {
                        xv = __ldg(xp + (size_t)rimg * IMG + c);
                        yv = __ldg(yp + (size_t)rimg * IMG + c);
                    }
                    wsd[m] = pk2(xv + yv, xv - yv);
                }
                goto havewin;
            }
            if (!vec) {
#pragma unroll
                for (int m = 0; m < 14; m++) wsd[m] = 0;
                goto havewin;
            }
        }
        {
            const float4* xr = reinterpret_cast<const float4*>(xp + (size_t)rimg * IMG + cb);
            const float4* yr = reinterpret_cast<const float4*>(yp + (size_t)rimg * IMG + cb);
#pragma unroll
            for (int v = 0; v < 5; v++) {
                const float4 fx = __ldg(xr + v);
                const float4 fy = __ldg(yr + v);
                const float xe[4] = { fx.x, fx.y, fx.z, fx.w };
                const float ye[4] = { fy.x, fy.y, fy.z, fy.w };
#pragma unroll
                for (int e = 0; e < 4; e++) {
                    const int i = 4 * v + e;       // col cb+i; window i in [3,17)
                    if (i >= 3 && i < 17) {
                        // (x+y, x-y) in one packed fma: (y,y)*(1,-1) + (x,x)
                        const u64 xx = pk2(xe[e], xe[e]);
                        const u64 yy = pk2(ye[e], ye[e]);
                        wsd[i - 3] = f2fma(yy, PM1, xx);
                    }
                }
            }
        }
    havewin:
        // MSE: owned rows r in [5,37); hi lane of wsd = D
        if (r >= 5 && r < 37) {
#pragma unroll
            for (int m = 5; m < 9; m++) msep = f2fma(wsd[m], wsd[m], msep);
        }

        // SD conv + store
        {
            u64 o0 = conv11(wsd + 0, G2), o1 = conv11(wsd + 1, G2);
            u64 o2 = conv11(wsd + 2, G2), o3 = conv11(wsd + 3, G2);
            float a0, b0, a1, b1;
            float4* p = reinterpret_cast<float4*>(&Hsd[r][q * 4]);
            upk(o0, a0, b0); upk(o1, a1, b1);
            p[0] = make_float4(a0, b0, a1, b1);
            upk(o2, a0, b0); upk(o3, a1, b1);
            p[1] = make_float4(a0, b0, a1, b1);
        }

        // transform window in place: (s,d) -> (s^2, d^2), then UV conv + store
#pragma unroll
        for (int m = 0; m < 14; m++) wsd[m] = f2mul(wsd[m], wsd[m]);
        {
            u64 o0 = conv11(wsd + 0, G2), o1 = conv11(wsd + 1, G2);
            u64 o2 = conv11(wsd + 2, G2), o3 = conv11(wsd + 3, G2);
            float a0, b0, a1, b1;
            float4* p = reinterpret_cast<float4*>(&Huv[r][q * 4]);
            upk(o0, a0, b0); upk(o1, a1, b1);
            p[0] = make_float4(a0, b0, a1, b1);
            upk(o2, a0, b0); upk(o3, a1, b1);
            p[1] = make_float4(a0, b0, a1, b1);
        }
    }
    return msep;
}

__global__ void __launch_bounds__(NT, 4) ssim_mse_kernel(
    const float* __restrict__ x, const float* __restrict__ y,
    float* __restrict__ out)
{
    __shared__ alignas(16) u64 Hsd[HROWS][HSTRIDE];
    __shared__ alignas(16) u64 Huv[HROWS][HSTRIDE];
    __shared__ float red_m[8], red_s[8];

    const int plane = blockIdx.z;
    const int row0  = blockIdx.y * TH;
    const int col0  = blockIdx.x * TW;
    const float* xp = x + (size_t)plane * (IMG * IMG);
    const float* yp = y + (size_t)plane * (IMG * IMG);
    const int tid = threadIdx.x;

    const u64 G2[6] = { pk2(GW[0], GW[0]), pk2(GW[1], GW[1]), pk2(GW[2], GW[2]),
                        pk2(GW[3], GW[3]), pk2(GW[4], GW[4]), pk2(GW[5], GW[5]) };
    const u64 PM1 = pk2(1.0f, -1.0f);
    const u64 MM1 = pk2(-1.0f, -1.0f);

    const bool xin = (blockIdx.x >= 1) && (blockIdx.x <= 6);
    const bool yin = (blockIdx.y >= 1) && (blockIdx.y <= 14);

    u64 msep;
    if (xin && yin) msep = phaseA<0>(xp, yp, row0, col0, tid, Hsd, Huv, G2, PM1);
    else if (xin)   msep = phaseA<1>(xp, yp, row0, col0, tid, Hsd, Huv, G2, PM1);
    else            msep = phaseA<2>(xp, yp, row0, col0, tid, Hsd, Huv, G2, PM1);

    float mse_lo, mse_acc;
    upk(msep, mse_lo, mse_acc);        // hi lane = sum D^2

    __syncthreads();

    // ---------------- Phase B: two-pass vertical conv ----------------
    const int col   = tid & 63;
    const int strip = tid >> 6;
    const int rb    = strip * 8;

    u64 ring[11];
    u64 vsd[8];

    // pass 1: SD stream
#pragma unroll
    for (int k = 0; k < 10; k++) ring[k] = Hsd[rb + k][col];
#pragma unroll
    for (int r = 0; r < 8; r++) {
        ring[(r + 10) % 11] = Hsd[rb + r + 10][col];
        u64 acc = f2mul(G2[5], ring[(r + 5) % 11]);
#pragma unroll
        for (int k = 0; k < 5; k++)
            acc = f2fma(G2[k], f2add(ring[(r + k) % 11], ring[(r + 10 - k) % 11]), acc);
        vsd[r] = acc;
    }

    // pass 2: UV stream + epilogue
    float ssim_acc = 0.f;
#pragma unroll
    for (int k = 0; k < 10; k++) ring[k] = Huv[rb + k][col];
#pragma unroll
    for (int r = 0; r < 8; r++) {
        ring[(r + 10) % 11] = Huv[rb + r + 10][col];
        u64 acc = f2mul(G2[5], ring[(r + 5) % 11]);
#pragma unroll
        for (int k = 0; k < 5; k++)
            acc = f2fma(G2[k], f2add(ring[(r + k) % 11], ring[(r + 10 - k) % 11]), acc);

        const u64 s2d2 = f2mul(vsd[r], vsd[r]);          // (S^2, D^2)
        const u64 varp = f2fma(s2d2, MM1, acc);          // (varS, varD)
        float S2, D2, varS, varD;
        upk(s2d2, S2, D2);
        upk(varp, varS, varD);
        const float A   = 0.5f * (S2 - D2);  // 2*mu1*mu2
        const float Msq = 0.5f * (S2 + D2);  // mu1^2 + mu2^2
        const float num = (A + C1F) * (0.5f * (varS - varD) + C2F);
        const float den = (Msq + C1F) * (0.5f * (varS + varD) + C2F);
        ssim_acc += __fdividef(num, den);
    }

    // ---------------- Reduction + fused finalize ----------------
#pragma unroll
    for (int o = 16; o > 0; o >>= 1) {
        mse_acc  += __shfl_down_sync(0xffffffffu, mse_acc,  o);
        ssim_acc += __shfl_down_sync(0xffffffffu, ssim_acc, o);
    }
    const int wid = tid >> 5;
    if ((tid & 31) == 0) { red_m[wid] = mse_acc; red_s[wid] = ssim_acc; }
    __syncthreads();
    if (tid < 32) {
        float m  = (tid < 8) ? red_m[tid] : 0.f;
        float ss = (tid < 8) ? red_s[tid] : 0.f;
#pragma unroll
        for (int o = 4; o > 0; o >>= 1) {
            m  += __shfl_down_sync(0xffffffffu, m,  o);
            ss += __shfl_down_sync(0xffffffffu, ss, o);
        }
        if (tid == 0) {
            atomicAdd(&g_acc[0], (double)m);
            atomicAdd(&g_acc[1], (double)ss);
            __threadfence();
            const unsigned c = atomicAdd(&g_count, 1u);
            if (c == NBLOCKS - 1) {
                __threadfence();
                const double mse  = g_acc[0] / NPIX;
                const double ssim = g_acc[1] / NPIX;
                out[0] = (float)(0.7 * mse + 0.3 * (1.0 - ssim));
                g_acc[0] = 0.0;
                g_acc[1] = 0.0;
                __threadfence();
                g_count = 0u;
            }
        }
    }
}

extern "C" void kernel_launch(void* const* d_in, const int* in_sizes, int n_in,
                              void* d_out, int out_size)
{
    const float* recon = (const float*)d_in[0];
    const float* orig  = (const float*)d_in[1];
    float* out = (float*)d_out;

    dim3 grid(IMG / TW, IMG / TH, NPLANES);   // 24576 blocks
    ssim_mse_kernel<<<grid, NT>>>(recon, orig, out);
}

// round 9
// speedup vs baseline: 1.9275x; 1.1079x over previous
#include <cuda_runtime.h>

#define IMG      512
#define TW       64
#define STRIPH   128
#define CHUNK    32
#define HB       42          // smem buffer rows
#define HSTRIDE  66          // 528B row stride, 16B-aligned float4 stores
#define NT       256
#define NPLANES  192
#define NBLOCKS  (8 * 4 * 192)
#define NPIX     (64.0 * 3.0 * 512.0 * 512.0)

typedef unsigned long long u64;

__device__ constexpr float GW[6] = {
    1.0283886e-3f, 7.5988485e-3f, 3.6000773e-2f, 1.0936073e-1f, 2.1300553e-1f,
    2.6601180e-1f
};

#define C1F 4.0e-4f
#define C2F 3.6e-3f

__device__ double g_acc[2];
__device__ unsigned int g_count;

// ---------- packed f32x2 helpers ----------
__device__ __forceinline__ u64 pk2(float lo, float hi) {
    u64 r; asm("mov.b64 %0,{%1,%2};" : "=l"(r) : "f"(lo), "f"(hi)); return r;
}
__device__ __forceinline__ void upk(u64 a, float& lo, float& hi) {
    asm("mov.b64 {%0,%1},%2;" : "=f"(lo), "=f"(hi) : "l"(a));
}
__device__ __forceinline__ u64 f2fma(u64 a, u64 b, u64 c) {
    u64 d; asm("fma.rn.f32x2 %0,%1,%2,%3;" : "=l"(d) : "l"(a), "l"(b), "l"(c)); return d;
}
__device__ __forceinline__ u64 f2add(u64 a, u64 b) {
    u64 d; asm("add.rn.f32x2 %0,%1,%2;" : "=l"(d) : "l"(a), "l"(b)); return d;
}
__device__ __forceinline__ u64 f2mul(u64 a, u64 b) {
    u64 d; asm("mul.rn.f32x2 %0,%1,%2;" : "=l"(d) : "l"(a), "l"(b)); return d;
}

// 11-tap symmetric conv on packed pairs
__device__ __forceinline__ u64 conv11(const u64* w, const u64* G2) {
    u64 acc = f2mul(G2[5], w[5]);
#pragma unroll
    for (int k = 0; k < 5; k++)
        acc = f2fma(G2[k], f2add(w[k], w[10 - k]), acc);
    return acc;
}

// ---------------- Phase A producer: nrows H-rows into buffer ----------------
// COLG: need column guards. ROWG: need image-row guards.
// MSE accumulated only for local rows rr in [mlo, mhi).
template <bool COLG, bool ROWG>
__device__ __forceinline__ u64 produceRows(
    const float* __restrict__ xp, const float* __restrict__ yp,
    int col0, int tid, int hb0, int rimg0, int nrows, int mlo, int mhi,
    u64 (*Hsd)[HSTRIDE], u64 (*Huv)[HSTRIDE], const u64* G2)
{
    u64 msep = 0;
    for (int s = tid; s < (nrows << 4); s += NT) {
        const int rr = s >> 4;
        const int q  = s & 15;
        const int hb = hb0 + rr;
        const int rimg = rimg0 + rr;
        const int cb   = col0 + q * 4 - 8;   // 16B aligned

        u64 wsd[14];
        bool rok = true, vec = true;
        if (ROWG) { rok = ((unsigned)rimg < IMG); vec = rok; }
        if (COLG) vec = vec && (cb >= 0) && (cb + 20 <= IMG);

        if (vec) {
            const float4* xr = reinterpret_cast<const float4*>(xp + (size_t)rimg * IMG + cb);
            const float4* yr = reinterpret_cast<const float4*>(yp + (size_t)rimg * IMG + cb);
#pragma unroll
            for (int v = 0; v < 5; v++) {
                const float4 fx = __ldg(xr + v);
                const float4 fy = __ldg(yr + v);
                const float xe[4] = { fx.x, fx.y, fx.z, fx.w };
                const float ye[4] = { fy.x, fy.y, fy.z, fy.w };
#pragma unroll
                for (int e = 0; e < 4; e++) {
                    const int i = 4 * v + e;       // col cb+i; window i in [3,17)
                    if (i >= 3 && i < 17)
                        wsd[i - 3] = pk2(xe[e] + ye[e], xe[e] - ye[e]);
                }
            }
        } else if (COLG && rok) {
            // scalar guarded: window cols cb+3 .. cb+16
#pragma unroll
            for (int m = 0; m < 14; m++) {
                const int c = cb + 3 + m;
                float xv = 0.f, yv = 0.f;
                if ((unsigned)c < IMG) {
                    xv = __ldg(xp + (size_t)rimg * IMG + c);
                    yv = __ldg(yp + (size_t)rimg * IMG + c);
                }
                wsd[m] = pk2(xv + yv, xv - yv);
            }
        } else {
#pragma unroll
            for (int m = 0; m < 14; m++) wsd[m] = 0;
        }

        // MSE: owned local rows only (hi lane of wsd = D)
        if (rr >= mlo && rr < mhi) {
#pragma unroll
            for (int m = 5; m < 9; m++) msep = f2fma(wsd[m], wsd[m], msep);
        }

        // SD conv + store
        {
            u64 o0 = conv11(wsd + 0, G2), o1 = conv11(wsd + 1, G2);
            u64 o2 = conv11(wsd + 2, G2), o3 = conv11(wsd + 3, G2);
            float a0, b0, a1, b1;
            float4* p = reinterpret_cast<float4*>(&Hsd[hb][q * 4]);
            upk(o0, a0, b0); upk(o1, a1, b1);
            p[0] = make_float4(a0, b0, a1, b1);
            upk(o2, a0, b0); upk(o3, a1, b1);
            p[1] = make_float4(a0, b0, a1, b1);
        }
        // square in place, UV conv + store
#pragma unroll
        for (int m = 0; m < 14; m++) wsd[m] = f2mul(wsd[m], wsd[m]);
        {
            u64 o0 = conv11(wsd + 0, G2), o1 = conv11(wsd + 1, G2);
            u64 o2 = conv11(wsd + 2, G2), o3 = conv11(wsd + 3, G2);
            float a0, b0, a1, b1;
            float4* p = reinterpret_cast<float4*>(&Huv[hb][q * 4]);
            upk(o0, a0, b0); upk(o1, a1, b1);
            p[0] = make_float4(a0, b0, a1, b1);
            upk(o2, a0, b0); upk(o3, a1, b1);
            p[1] = make_float4(a0, b0, a1, b1);
        }
    }
    return msep;
}

__device__ __forceinline__ u64 produceDispatch(
    bool colg, bool rowg,
    const float* __restrict__ xp, const float* __restrict__ yp,
    int col0, int tid, int hb0, int rimg0, int nrows, int mlo, int mhi,
    u64 (*Hsd)[HSTRIDE], u64 (*Huv)[HSTRIDE], const u64* G2)
{
    if (colg) {
        if (rowg) return produceRows<true , true >(xp, yp, col0, tid, hb0, rimg0, nrows, mlo, mhi, Hsd, Huv, G2);
        else      return produceRows<true , false>(xp, yp, col0, tid, hb0, rimg0, nrows, mlo, mhi, Hsd, Huv, G2);
    } else {
        if (rowg) return produceRows<false, true >(xp, yp, col0, tid, hb0, rimg0, nrows, mlo, mhi, Hsd, Huv, G2);
        else      return produceRows<false, false>(xp, yp, col0, tid, hb0, rimg0, nrows, mlo, mhi, Hsd, Huv, G2);
    }
}

// ---------------- Phase B consumer: one 64x32 chunk ----------------
__device__ __forceinline__ float consumeChunk(
    int tid, u64 (*Hsd)[HSTRIDE], u64 (*Huv)[HSTRIDE], const u64* G2, u64 MM1)
{
    const int col   = tid & 63;
    const int strip = tid >> 6;
    const int rb    = strip * 8;

    u64 ring[11];
    u64 vsd[8];

    // pass 1: SD stream
#pragma unroll
    for (int k = 0; k < 10; k++) ring[k] = Hsd[rb + k][col];
#pragma unroll
    for (int r = 0; r < 8; r++) {
        ring[(r + 10) % 11] = Hsd[rb + r + 10][col];
        u64 acc = f2mul(G2[5], ring[(r + 5) % 11]);
#pragma unroll
        for (int k = 0; k < 5; k++)
            acc = f2fma(G2[k], f2add(ring[(r + k) % 11], ring[(r + 10 - k) % 11]), acc);
        vsd[r] = acc;
    }

    // pass 2: UV stream + epilogue
    float ssim_acc = 0.f;
#pragma unroll
    for (int k = 0; k < 10; k++) ring[k] = Huv[rb + k][col];
#pragma unroll
    for (int r = 0; r < 8; r++) {
        ring[(r + 10) % 11] = Huv[rb + r + 10][col];
        u64 acc = f2mul(G2[5], ring[(r + 5) % 11]);
#pragma unroll
        for (int k = 0; k < 5; k++)
            acc = f2fma(G2[k], f2add(ring[(r + k) % 11], ring[(r + 10 - k) % 11]), acc);

        const u64 s2d2 = f2mul(vsd[r], vsd[r]);          // (S^2, D^2)
        const u64 varp = f2fma(s2d2, MM1, acc);          // (varS, varD)
        float S2, D2, varS, varD;
        upk(s2d2, S2, D2);
        upk(varp, varS, varD);
        const float A   = 0.5f * (S2 - D2);  // 2*mu1*mu2
        const float Msq = 0.5f * (S2 + D2);  // mu1^2 + mu2^2
        const float num = (A + C1F) * (0.5f * (varS - varD) + C2F);
        const float den = (Msq + C1F) * (0.5f * (varS + varD) + C2F);
        ssim_acc += __fdividef(num, den);
    }
    return ssim_acc;
}

__global__ void __launch_bounds__(NT, 4) ssim_mse_kernel(
    const float* __restrict__ x, const float* __restrict__ y,
    float* __restrict__ out)
{
    __shared__ alignas(16) u64 Hsd[HB][HSTRIDE];
    __shared__ alignas(16) u64 Huv[HB][HSTRIDE];
    __shared__ float red_m[8], red_s[8];

    const int plane = blockIdx.z;
    const int row0  = blockIdx.y * STRIPH;
    const int col0  = blockIdx.x * TW;
    const float* xp = x + (size_t)plane * (IMG * IMG);
    const float* yp = y + (size_t)plane * (IMG * IMG);
    const int tid = threadIdx.x;

    const u64 G2[6] = { pk2(GW[0], GW[0]), pk2(GW[1], GW[1]), pk2(GW[2], GW[2]),
                        pk2(GW[3], GW[3]), pk2(GW[4], GW[4]), pk2(GW[5], GW[5]) };
    const u64 MM1 = pk2(-1.0f, -1.0f);

    const bool colg = (blockIdx.x == 0) || (blockIdx.x == 7);

    u64 msep = 0;
    float ssim_acc = 0.f;

    // chunk 0: fill all 42 buffer rows (image rows row0-5 .. row0+36)
    msep = produceDispatch(colg, blockIdx.y == 0,
                           xp, yp, col0, tid, 0, row0 - 5, HB, 5, HB,
                           Hsd, Huv, G2);
    __syncthreads();
    ssim_acc += consumeChunk(tid, Hsd, Huv, G2, MM1);

#pragma unroll
    for (int c = 1; c < STRIPH / CHUNK; c++) {
        __syncthreads();                       // consume done before copy
        // slide buffer: rows 32..41 -> 0..9
        for (int i = tid; i < 640; i += NT) {
            const int rw = i >> 6, cl = i & 63;
            Hsd[rw][cl] = Hsd[rw + 32][cl];
            Huv[rw][cl] = Huv[rw + 32][cl];
        }
        __syncthreads();                       // copy done before produce overwrites
        const bool rowg = (c == 3) && (blockIdx.y == 3);
        const int  mhi  = (c == 3) ? 27 : 32;  // rows past strip owned by next strip
        msep = f2add(msep,
            produceDispatch(colg, rowg,
                            xp, yp, col0, tid, 10, row0 + 32 * c + 5, CHUNK, 0, mhi,
                            Hsd, Huv, G2));
        __syncthreads();                       // produce done before consume
        ssim_acc += consumeChunk(tid, Hsd, Huv, G2, MM1);
    }

    float mse_lo, mse_acc;
    upk(msep, mse_lo, mse_acc);                // hi lane = sum D^2

    // ---------------- Reduction + fused finalize ----------------
#pragma unroll
    for (int o = 16; o > 0; o >>= 1) {
        mse_acc  += __shfl_down_sync(0xffffffffu, mse_acc,  o);
        ssim_acc += __shfl_down_sync(0xffffffffu, ssim_acc, o);
    }
    const int wid = tid >> 5;
    if ((tid & 31) == 0) { red_m[wid] = mse_acc; red_s[wid] = ssim_acc; }
    __syncthreads();
    if (tid < 32) {
        float m  = (tid < 8) ? red_m[tid] : 0.f;
        float ss = (tid < 8) ? red_s[tid] : 0.f;
#pragma unroll
        for (int o = 4; o > 0; o >>= 1) {
            m  += __shfl_down_sync(0xffffffffu, m,  o);
            ss += __shfl_down_sync(0xffffffffu, ss, o);
        }
        if (tid == 0) {
            atomicAdd(&g_acc[0], (double)m);
            atomicAdd(&g_acc[1], (double)ss);
            __threadfence();
            const unsigned c = atomicAdd(&g_count, 1u);
            if (c == NBLOCKS - 1) {
                __threadfence();
                const double mse  = g_acc[0] / NPIX;
                const double ssim = g_acc[1] / NPIX;
                out[0] = (float)(0.7 * mse + 0.3 * (1.0 - ssim));
                g_acc[0] = 0.0;
                g_acc[1] = 0.0;
                __threadfence();
                g_count = 0u;
            }
        }
    }
}

extern "C" void kernel_launch(void* const* d_in, const int* in_sizes, int n_in,
                              void* d_out, int out_size)
{
    const float* recon = (const float*)d_in[0];
    const float* orig  = (const float*)d_in[1];
    float* out = (float*)d_out;

    dim3 grid(IMG / TW, IMG / STRIPH, NPLANES);   // 8 x 4 x 192 = 6144 blocks
    ssim_mse_kernel<<<grid, NT>>>(recon, orig, out);
}